// round 1
// baseline (speedup 1.0000x reference)
#include <cuda_runtime.h>
#include <math_constants.h>

// Problem constants (fixed by the dataset): B=4, S=2048, d_in=d_out=1024, fp32.
#define BATCH 4
#define SEQ   2048
#define DMODEL 1024

#define BM 128
#define BN 128
#define BK 8
#define PAD 4   // smem row pad (keeps 16B alignment: 132 floats = 528B)

// Scratch (allocation-free: __device__ globals)
__device__ float g_Q[(size_t)BATCH * SEQ * DMODEL];
__device__ float g_K[(size_t)BATCH * SEQ * DMODEL];
__device__ float g_V[(size_t)BATCH * SEQ * DMODEL];
__device__ float g_P[(size_t)BATCH * SEQ * SEQ];

// ---------------------------------------------------------------------------
// C[M,N] = alpha * A @ B^T    A: [M,K] row-major (lda=K), B: [N,K] row-major (ldb=K)
// causalSkip: skip tiles fully above the diagonal (used for Q@K^T). Masked
// entries inside the diagonal tile are written unmasked — the softmax kernel
// only reads k <= q, so they are never consumed.
// ---------------------------------------------------------------------------
__global__ __launch_bounds__(256) void gemm_nt(
    const float* __restrict__ A, const float* __restrict__ B, float* __restrict__ C,
    int K, int ldc,
    long sA, long sB, long sC, float alpha, int causalSkip)
{
    const int m0 = blockIdx.y * BM;
    const int n0 = blockIdx.x * BN;
    if (causalSkip && n0 >= m0 + BM) return;

    A += (size_t)blockIdx.z * sA;
    B += (size_t)blockIdx.z * sB;
    C += (size_t)blockIdx.z * sC;

    __shared__ float As[BK][BM + PAD];
    __shared__ float Bs[BK][BN + PAD];

    const int tid = threadIdx.x;
    const int tx = tid & 15;        // 0..15 -> n microtile
    const int ty = tid >> 4;        // 0..15 -> m microtile
    const int lrow = tid >> 1;      // 0..127 row to load
    const int lk4  = (tid & 1) << 2;// 0 or 4

    const float* Ap = A + (size_t)(m0 + lrow) * K + lk4;
    const float* Bp = B + (size_t)(n0 + lrow) * K + lk4;

    float acc[8][8];
#pragma unroll
    for (int i = 0; i < 8; i++)
#pragma unroll
        for (int j = 0; j < 8; j++) acc[i][j] = 0.f;

    for (int k0 = 0; k0 < K; k0 += BK) {
        float4 av = *(const float4*)(Ap + k0);
        float4 bv = *(const float4*)(Bp + k0);
        As[lk4 + 0][lrow] = av.x; As[lk4 + 1][lrow] = av.y;
        As[lk4 + 2][lrow] = av.z; As[lk4 + 3][lrow] = av.w;
        Bs[lk4 + 0][lrow] = bv.x; Bs[lk4 + 1][lrow] = bv.y;
        Bs[lk4 + 2][lrow] = bv.z; Bs[lk4 + 3][lrow] = bv.w;
        __syncthreads();
#pragma unroll
        for (int kk = 0; kk < BK; kk++) {
            float a[8], b[8];
            *(float4*)&a[0] = *(const float4*)&As[kk][ty * 8];
            *(float4*)&a[4] = *(const float4*)&As[kk][ty * 8 + 4];
            *(float4*)&b[0] = *(const float4*)&Bs[kk][tx * 8];
            *(float4*)&b[4] = *(const float4*)&Bs[kk][tx * 8 + 4];
#pragma unroll
            for (int i = 0; i < 8; i++)
#pragma unroll
                for (int j = 0; j < 8; j++)
                    acc[i][j] = fmaf(a[i], b[j], acc[i][j]);
        }
        __syncthreads();
    }

#pragma unroll
    for (int i = 0; i < 8; i++) {
        const int m = m0 + ty * 8 + i;
        float4 v0 = make_float4(acc[i][0] * alpha, acc[i][1] * alpha,
                                acc[i][2] * alpha, acc[i][3] * alpha);
        float4 v1 = make_float4(acc[i][4] * alpha, acc[i][5] * alpha,
                                acc[i][6] * alpha, acc[i][7] * alpha);
        *(float4*)&C[(size_t)m * ldc + n0 + tx * 8]     = v0;
        *(float4*)&C[(size_t)m * ldc + n0 + tx * 8 + 4] = v1;
    }
}

// ---------------------------------------------------------------------------
// C[M,N] = A @ B    A: [M,K] row-major (lda=K), B: [K,N] row-major (ldb=N)
// causalK: truncate the k loop at m0+BM (P is exactly zero for k > q; the
// softmax kernel zero-fills up to the diagonal tile boundary).
// ---------------------------------------------------------------------------
__global__ __launch_bounds__(256) void gemm_nn(
    const float* __restrict__ A, const float* __restrict__ B, float* __restrict__ C,
    int N, int K,
    long sA, long sB, long sC, int causalK)
{
    const int m0 = blockIdx.y * BM;
    const int n0 = blockIdx.x * BN;

    A += (size_t)blockIdx.z * sA;
    B += (size_t)blockIdx.z * sB;
    C += (size_t)blockIdx.z * sC;

    const int kEnd = causalK ? min(K, m0 + BM) : K;

    __shared__ float As[BK][BM + PAD];
    __shared__ float Bs[BK][BN + PAD];

    const int tid = threadIdx.x;
    const int tx = tid & 15;
    const int ty = tid >> 4;
    const int lrow = tid >> 1;       // A load row
    const int lk4  = (tid & 1) << 2;
    const int krow = tid >> 5;       // B load row 0..7
    const int nq   = (tid & 31) << 2;// B load col 0..124

    float acc[8][8];
#pragma unroll
    for (int i = 0; i < 8; i++)
#pragma unroll
        for (int j = 0; j < 8; j++) acc[i][j] = 0.f;

    for (int k0 = 0; k0 < kEnd; k0 += BK) {
        float4 av = *(const float4*)&A[(size_t)(m0 + lrow) * K + k0 + lk4];
        float4 bv = *(const float4*)&B[(size_t)(k0 + krow) * N + n0 + nq];
        As[lk4 + 0][lrow] = av.x; As[lk4 + 1][lrow] = av.y;
        As[lk4 + 2][lrow] = av.z; As[lk4 + 3][lrow] = av.w;
        *(float4*)&Bs[krow][nq] = bv;
        __syncthreads();
#pragma unroll
        for (int kk = 0; kk < BK; kk++) {
            float a[8], b[8];
            *(float4*)&a[0] = *(const float4*)&As[kk][ty * 8];
            *(float4*)&a[4] = *(const float4*)&As[kk][ty * 8 + 4];
            *(float4*)&b[0] = *(const float4*)&Bs[kk][tx * 8];
            *(float4*)&b[4] = *(const float4*)&Bs[kk][tx * 8 + 4];
#pragma unroll
            for (int i = 0; i < 8; i++)
#pragma unroll
                for (int j = 0; j < 8; j++)
                    acc[i][j] = fmaf(a[i], b[j], acc[i][j]);
        }
        __syncthreads();
    }

#pragma unroll
    for (int i = 0; i < 8; i++) {
        const int m = m0 + ty * 8 + i;
        float4 v0 = make_float4(acc[i][0], acc[i][1], acc[i][2], acc[i][3]);
        float4 v1 = make_float4(acc[i][4], acc[i][5], acc[i][6], acc[i][7]);
        *(float4*)&C[(size_t)m * N + n0 + tx * 8]     = v0;
        *(float4*)&C[(size_t)m * N + n0 + tx * 8 + 4] = v1;
    }
}

// ---------------------------------------------------------------------------
// In-place causal row softmax over P[b, q, :]. Only reads k <= q (entries
// beyond are garbage from the scores GEMM). Zero-fills k in (q, roundup(q+1,
// BM)) so the truncated-k P@V GEMM sees exact zeros in the diagonal tile.
// ---------------------------------------------------------------------------
__global__ __launch_bounds__(256) void softmax_causal(float* __restrict__ P, int S)
{
    const int q = blockIdx.x;
    const int b = blockIdx.y;
    float* row = P + ((size_t)b * S + q) * S;
    const int len = q + 1;
    const int tid = threadIdx.x;

    __shared__ float sred[8];
    __shared__ float sbcast;

    float vals[8];
    int n = 0;
    float m = -CUDART_INF_F;
    for (int i = tid; i < len; i += 256) {
        float v = row[i];
        vals[n++] = v;
        m = fmaxf(m, v);
    }
#pragma unroll
    for (int o = 16; o; o >>= 1) m = fmaxf(m, __shfl_xor_sync(0xffffffffu, m, o));
    if ((tid & 31) == 0) sred[tid >> 5] = m;
    __syncthreads();
    if (tid == 0) {
        float t = sred[0];
#pragma unroll
        for (int w = 1; w < 8; w++) t = fmaxf(t, sred[w]);
        sbcast = t;
    }
    __syncthreads();
    m = sbcast;

    float s = 0.f;
#pragma unroll
    for (int k = 0; k < 8; k++) {
        if (k < n) {
            float e = expf(vals[k] - m);
            vals[k] = e;
            s += e;
        }
    }
#pragma unroll
    for (int o = 16; o; o >>= 1) s += __shfl_xor_sync(0xffffffffu, s, o);
    __syncthreads();   // protect sred reuse
    if ((tid & 31) == 0) sred[tid >> 5] = s;
    __syncthreads();
    if (tid == 0) {
        float t = 0.f;
#pragma unroll
        for (int w = 0; w < 8; w++) t += sred[w];
        sbcast = 1.f / t;
    }
    __syncthreads();
    const float inv = sbcast;

    n = 0;
    for (int i = tid; i < len; i += 256) row[i] = vals[n++] * inv;

    const int tileEnd = ((q >> 7) + 1) << 7;   // roundup(q+1, 128)
    for (int i = len + tid; i < tileEnd; i += 256) row[i] = 0.f;
}

// ---------------------------------------------------------------------------
extern "C" void kernel_launch(void* const* d_in, const int* in_sizes, int n_in,
                              void* d_out, int out_size)
{
    const float* x  = (const float*)d_in[0];
    const float* Wq = (const float*)d_in[1];
    const float* Wk = (const float*)d_in[2];
    const float* Wv = (const float*)d_in[3];
    float* out = (float*)d_out;

    float *Q, *K, *V, *P;
    cudaGetSymbolAddress((void**)&Q, g_Q);
    cudaGetSymbolAddress((void**)&K, g_K);
    cudaGetSymbolAddress((void**)&V, g_V);
    cudaGetSymbolAddress((void**)&P, g_P);

    const long SD = (long)SEQ * DMODEL;
    const long SS = (long)SEQ * SEQ;
    dim3 blk(256);

    // 1) QKV projections: [B*S, d] @ W^T, one big GEMM each
    dim3 gproj(DMODEL / BN, (BATCH * SEQ) / BM, 1);
    gemm_nt<<<gproj, blk>>>(x, Wq, Q, DMODEL, DMODEL, 0, 0, 0, 1.f, 0);
    gemm_nt<<<gproj, blk>>>(x, Wk, K, DMODEL, DMODEL, 0, 0, 0, 1.f, 0);
    gemm_nt<<<gproj, blk>>>(x, Wv, V, DMODEL, DMODEL, 0, 0, 0, 1.f, 0);

    // 2) Scores: P[b] = (1/32) * Q[b] @ K[b]^T, causal tile skip
    dim3 gsc(SEQ / BN, SEQ / BM, BATCH);
    gemm_nt<<<gsc, blk>>>(Q, K, P, DMODEL, SEQ, SD, SD, SS, 0.03125f, 1);

    // 3) Causal softmax (in place, zero-fills to diagonal tile boundary)
    softmax_causal<<<dim3(SEQ, BATCH), blk>>>(P, SEQ);

    // 4) O[b] = P[b] @ V[b], k loop truncated at diagonal tile
    dim3 gpv(DMODEL / BN, SEQ / BM, BATCH);
    gemm_nn<<<gpv, blk>>>(P, V, out, DMODEL, SEQ, SS, SD, SD, 1);
}

// round 2
// speedup vs baseline: 1.0013x; 1.0013x over previous
#include <cuda_runtime.h>
#include <math_constants.h>

// Problem constants (fixed by the dataset): B=4, S=2048, d_in=d_out=1024, fp32.
#define BATCH 4
#define SEQ   2048
#define DMODEL 1024

#define BM 128
#define BN 128
#define BK 8
#define PAD 4   // smem row pad (keeps 16B alignment: 132 floats = 528B)

// Scratch (allocation-free: __device__ globals)
__device__ float g_Q[(size_t)BATCH * SEQ * DMODEL];
__device__ float g_K[(size_t)BATCH * SEQ * DMODEL];
__device__ float g_V[(size_t)BATCH * SEQ * DMODEL];
__device__ float g_P[(size_t)BATCH * SEQ * SEQ];

// ---------------------------------------------------------------------------
// C[M,N] = alpha * A @ B^T    A: [M,K] row-major (lda=K), B: [N,K] row-major (ldb=K)
// causalSkip: skip tiles fully above the diagonal (used for Q@K^T). Masked
// entries inside the diagonal tile are written unmasked — the softmax kernel
// only reads k <= q, so they are never consumed.
// ---------------------------------------------------------------------------
__global__ __launch_bounds__(256) void gemm_nt(
    const float* __restrict__ A, const float* __restrict__ B, float* __restrict__ C,
    int K, int ldc,
    long sA, long sB, long sC, float alpha, int causalSkip)
{
    const int m0 = blockIdx.y * BM;
    const int n0 = blockIdx.x * BN;
    if (causalSkip && n0 >= m0 + BM) return;

    A += (size_t)blockIdx.z * sA;
    B += (size_t)blockIdx.z * sB;
    C += (size_t)blockIdx.z * sC;

    __shared__ float As[BK][BM + PAD];
    __shared__ float Bs[BK][BN + PAD];

    const int tid = threadIdx.x;
    const int tx = tid & 15;        // 0..15 -> n microtile
    const int ty = tid >> 4;        // 0..15 -> m microtile
    const int lrow = tid >> 1;      // 0..127 row to load
    const int lk4  = (tid & 1) << 2;// 0 or 4

    const float* Ap = A + (size_t)(m0 + lrow) * K + lk4;
    const float* Bp = B + (size_t)(n0 + lrow) * K + lk4;

    float acc[8][8];
#pragma unroll
    for (int i = 0; i < 8; i++)
#pragma unroll
        for (int j = 0; j < 8; j++) acc[i][j] = 0.f;

    for (int k0 = 0; k0 < K; k0 += BK) {
        float4 av = *(const float4*)(Ap + k0);
        float4 bv = *(const float4*)(Bp + k0);
        As[lk4 + 0][lrow] = av.x; As[lk4 + 1][lrow] = av.y;
        As[lk4 + 2][lrow] = av.z; As[lk4 + 3][lrow] = av.w;
        Bs[lk4 + 0][lrow] = bv.x; Bs[lk4 + 1][lrow] = bv.y;
        Bs[lk4 + 2][lrow] = bv.z; Bs[lk4 + 3][lrow] = bv.w;
        __syncthreads();
#pragma unroll
        for (int kk = 0; kk < BK; kk++) {
            float a[8], b[8];
            *(float4*)&a[0] = *(const float4*)&As[kk][ty * 8];
            *(float4*)&a[4] = *(const float4*)&As[kk][ty * 8 + 4];
            *(float4*)&b[0] = *(const float4*)&Bs[kk][tx * 8];
            *(float4*)&b[4] = *(const float4*)&Bs[kk][tx * 8 + 4];
#pragma unroll
            for (int i = 0; i < 8; i++)
#pragma unroll
                for (int j = 0; j < 8; j++)
                    acc[i][j] = fmaf(a[i], b[j], acc[i][j]);
        }
        __syncthreads();
    }

#pragma unroll
    for (int i = 0; i < 8; i++) {
        const int m = m0 + ty * 8 + i;
        float4 v0 = make_float4(acc[i][0] * alpha, acc[i][1] * alpha,
                                acc[i][2] * alpha, acc[i][3] * alpha);
        float4 v1 = make_float4(acc[i][4] * alpha, acc[i][5] * alpha,
                                acc[i][6] * alpha, acc[i][7] * alpha);
        *(float4*)&C[(size_t)m * ldc + n0 + tx * 8]     = v0;
        *(float4*)&C[(size_t)m * ldc + n0 + tx * 8 + 4] = v1;
    }
}

// ---------------------------------------------------------------------------
// C[M,N] = A @ B    A: [M,K] row-major (lda=K), B: [K,N] row-major (ldb=N)
// causalK: truncate the k loop at m0+BM (P is exactly zero for k > q; the
// softmax kernel zero-fills up to the diagonal tile boundary).
// ---------------------------------------------------------------------------
__global__ __launch_bounds__(256) void gemm_nn(
    const float* __restrict__ A, const float* __restrict__ B, float* __restrict__ C,
    int N, int K,
    long sA, long sB, long sC, int causalK)
{
    const int m0 = blockIdx.y * BM;
    const int n0 = blockIdx.x * BN;

    A += (size_t)blockIdx.z * sA;
    B += (size_t)blockIdx.z * sB;
    C += (size_t)blockIdx.z * sC;

    const int kEnd = causalK ? min(K, m0 + BM) : K;

    __shared__ float As[BK][BM + PAD];
    __shared__ float Bs[BK][BN + PAD];

    const int tid = threadIdx.x;
    const int tx = tid & 15;
    const int ty = tid >> 4;
    const int lrow = tid >> 1;       // A load row
    const int lk4  = (tid & 1) << 2;
    const int krow = tid >> 5;       // B load row 0..7
    const int nq   = (tid & 31) << 2;// B load col 0..124

    float acc[8][8];
#pragma unroll
    for (int i = 0; i < 8; i++)
#pragma unroll
        for (int j = 0; j < 8; j++) acc[i][j] = 0.f;

    for (int k0 = 0; k0 < kEnd; k0 += BK) {
        float4 av = *(const float4*)&A[(size_t)(m0 + lrow) * K + k0 + lk4];
        float4 bv = *(const float4*)&B[(size_t)(k0 + krow) * N + n0 + nq];
        As[lk4 + 0][lrow] = av.x; As[lk4 + 1][lrow] = av.y;
        As[lk4 + 2][lrow] = av.z; As[lk4 + 3][lrow] = av.w;
        *(float4*)&Bs[krow][nq] = bv;
        __syncthreads();
#pragma unroll
        for (int kk = 0; kk < BK; kk++) {
            float a[8], b[8];
            *(float4*)&a[0] = *(const float4*)&As[kk][ty * 8];
            *(float4*)&a[4] = *(const float4*)&As[kk][ty * 8 + 4];
            *(float4*)&b[0] = *(const float4*)&Bs[kk][tx * 8];
            *(float4*)&b[4] = *(const float4*)&Bs[kk][tx * 8 + 4];
#pragma unroll
            for (int i = 0; i < 8; i++)
#pragma unroll
                for (int j = 0; j < 8; j++)
                    acc[i][j] = fmaf(a[i], b[j], acc[i][j]);
        }
        __syncthreads();
    }

#pragma unroll
    for (int i = 0; i < 8; i++) {
        const int m = m0 + ty * 8 + i;
        float4 v0 = make_float4(acc[i][0], acc[i][1], acc[i][2], acc[i][3]);
        float4 v1 = make_float4(acc[i][4], acc[i][5], acc[i][6], acc[i][7]);
        *(float4*)&C[(size_t)m * N + n0 + tx * 8]     = v0;
        *(float4*)&C[(size_t)m * N + n0 + tx * 8 + 4] = v1;
    }
}

// ---------------------------------------------------------------------------
// In-place causal row softmax over P[b, q, :]. Only reads k <= q (entries
// beyond are garbage from the scores GEMM). Zero-fills k in (q, roundup(q+1,
// BM)) so the truncated-k P@V GEMM sees exact zeros in the diagonal tile.
// ---------------------------------------------------------------------------
__global__ __launch_bounds__(256) void softmax_causal(float* __restrict__ P, int S)
{
    const int q = blockIdx.x;
    const int b = blockIdx.y;
    float* row = P + ((size_t)b * S + q) * S;
    const int len = q + 1;
    const int tid = threadIdx.x;

    __shared__ float sred[8];
    __shared__ float sbcast;

    float vals[8];
    int n = 0;
    float m = -CUDART_INF_F;
    for (int i = tid; i < len; i += 256) {
        float v = row[i];
        vals[n++] = v;
        m = fmaxf(m, v);
    }
#pragma unroll
    for (int o = 16; o; o >>= 1) m = fmaxf(m, __shfl_xor_sync(0xffffffffu, m, o));
    if ((tid & 31) == 0) sred[tid >> 5] = m;
    __syncthreads();
    if (tid == 0) {
        float t = sred[0];
#pragma unroll
        for (int w = 1; w < 8; w++) t = fmaxf(t, sred[w]);
        sbcast = t;
    }
    __syncthreads();
    m = sbcast;

    float s = 0.f;
#pragma unroll
    for (int k = 0; k < 8; k++) {
        if (k < n) {
            float e = expf(vals[k] - m);
            vals[k] = e;
            s += e;
        }
    }
#pragma unroll
    for (int o = 16; o; o >>= 1) s += __shfl_xor_sync(0xffffffffu, s, o);
    __syncthreads();   // protect sred reuse
    if ((tid & 31) == 0) sred[tid >> 5] = s;
    __syncthreads();
    if (tid == 0) {
        float t = 0.f;
#pragma unroll
        for (int w = 0; w < 8; w++) t += sred[w];
        sbcast = 1.f / t;
    }
    __syncthreads();
    const float inv = sbcast;

    n = 0;
    for (int i = tid; i < len; i += 256) row[i] = vals[n++] * inv;

    const int tileEnd = ((q >> 7) + 1) << 7;   // roundup(q+1, 128)
    for (int i = len + tid; i < tileEnd; i += 256) row[i] = 0.f;
}

// ---------------------------------------------------------------------------
extern "C" void kernel_launch(void* const* d_in, const int* in_sizes, int n_in,
                              void* d_out, int out_size)
{
    const float* x  = (const float*)d_in[0];
    const float* Wq = (const float*)d_in[1];
    const float* Wk = (const float*)d_in[2];
    const float* Wv = (const float*)d_in[3];
    float* out = (float*)d_out;

    float *Q, *K, *V, *P;
    cudaGetSymbolAddress((void**)&Q, g_Q);
    cudaGetSymbolAddress((void**)&K, g_K);
    cudaGetSymbolAddress((void**)&V, g_V);
    cudaGetSymbolAddress((void**)&P, g_P);

    const long SD = (long)SEQ * DMODEL;
    const long SS = (long)SEQ * SEQ;
    dim3 blk(256);

    // 1) QKV projections: [B*S, d] @ W^T, one big GEMM each
    dim3 gproj(DMODEL / BN, (BATCH * SEQ) / BM, 1);
    gemm_nt<<<gproj, blk>>>(x, Wq, Q, DMODEL, DMODEL, 0, 0, 0, 1.f, 0);
    gemm_nt<<<gproj, blk>>>(x, Wk, K, DMODEL, DMODEL, 0, 0, 0, 1.f, 0);
    gemm_nt<<<gproj, blk>>>(x, Wv, V, DMODEL, DMODEL, 0, 0, 0, 1.f, 0);

    // 2) Scores: P[b] = (1/32) * Q[b] @ K[b]^T, causal tile skip
    dim3 gsc(SEQ / BN, SEQ / BM, BATCH);
    gemm_nt<<<gsc, blk>>>(Q, K, P, DMODEL, SEQ, SD, SD, SS, 0.03125f, 1);

    // 3) Causal softmax (in place, zero-fills to diagonal tile boundary)
    softmax_causal<<<dim3(SEQ, BATCH), blk>>>(P, SEQ);

    // 4) O[b] = P[b] @ V[b], k loop truncated at diagonal tile
    dim3 gpv(DMODEL / BN, SEQ / BM, BATCH);
    gemm_nn<<<gpv, blk>>>(P, V, out, DMODEL, SEQ, SS, SD, SD, 1);
}

// round 4
// speedup vs baseline: 3.0222x; 3.0182x over previous
#include <cuda_runtime.h>
#include <cuda_bf16.h>
#include <math_constants.h>
#include <cstdint>

#define BATCH 4
#define SEQ   2048
#define DM    1024

#define BM 128
#define BN 128
#define BK 32                      // bf16 per chunk (64 bytes per row)
#define STAGES 4
#define MAT_BYTES (128 * 64)       // one 128x32 bf16 matrix = 8192 B
#define STAGE_BYTES (4 * MAT_BYTES)        // Ahi, Alo, Bhi, Blo = 32768 B
#define SMEM_TOTAL (STAGES * STAGE_BYTES)  // 131072 B

// ---------------------------------------------------------------------------
// Scratch (allocation-free)
// ---------------------------------------------------------------------------
__device__ __nv_bfloat16 g_xhi[(size_t)BATCH*SEQ*DM];
__device__ __nv_bfloat16 g_xlo[(size_t)BATCH*SEQ*DM];
__device__ __nv_bfloat16 g_Whi[(size_t)3*DM*DM];
__device__ __nv_bfloat16 g_Wlo[(size_t)3*DM*DM];
__device__ __nv_bfloat16 g_QKVhi[(size_t)3*BATCH*SEQ*DM];
__device__ __nv_bfloat16 g_QKVlo[(size_t)3*BATCH*SEQ*DM];
__device__ __nv_bfloat16 g_Vthi[(size_t)BATCH*DM*SEQ];
__device__ __nv_bfloat16 g_Vtlo[(size_t)BATCH*DM*SEQ];
__device__ float         g_P  [(size_t)BATCH*SEQ*SEQ];
__device__ __nv_bfloat16 g_Phi[(size_t)BATCH*SEQ*SEQ];
__device__ __nv_bfloat16 g_Plo[(size_t)BATCH*SEQ*SEQ];

// ---------------------------------------------------------------------------
// PTX helpers (all base-sm_80+ features: cp.async, ldmatrix, mma.sync)
// ---------------------------------------------------------------------------
__device__ __forceinline__ uint32_t smem_u32(const void* p) {
    uint32_t a;
    asm("{ .reg .u64 t; cvta.to.shared.u64 t, %1; cvt.u32.u64 %0, t; }" : "=r"(a) : "l"(p));
    return a;
}
__device__ __forceinline__ void cp_async16(uint32_t s, const void* g) {
    asm volatile("cp.async.cg.shared.global [%0], [%1], 16;" :: "r"(s), "l"(g));
}
#define CP_COMMIT() asm volatile("cp.async.commit_group;" ::: "memory")
#define CP_WAIT2()  asm volatile("cp.async.wait_group 2;" ::: "memory")
#define CP_WAIT0()  asm volatile("cp.async.wait_group 0;" ::: "memory")

__device__ __forceinline__ void ldmx4(uint32_t& r0, uint32_t& r1, uint32_t& r2, uint32_t& r3,
                                      uint32_t a) {
    asm volatile("ldmatrix.sync.aligned.m8n8.x4.shared.b16 {%0,%1,%2,%3}, [%4];"
        : "=r"(r0), "=r"(r1), "=r"(r2), "=r"(r3) : "r"(a));
}
__device__ __forceinline__ void ldmx2(uint32_t& r0, uint32_t& r1, uint32_t a) {
    asm volatile("ldmatrix.sync.aligned.m8n8.x2.shared.b16 {%0,%1}, [%2];"
        : "=r"(r0), "=r"(r1) : "r"(a));
}
__device__ __forceinline__ void mma16816(float* c, const uint32_t* a, const uint32_t* b) {
    asm volatile("mma.sync.aligned.m16n8k16.row.col.f32.bf16.bf16.f32 "
        "{%0,%1,%2,%3}, {%4,%5,%6,%7}, {%8,%9}, {%0,%1,%2,%3};"
        : "+f"(c[0]), "+f"(c[1]), "+f"(c[2]), "+f"(c[3])
        : "r"(a[0]), "r"(a[1]), "r"(a[2]), "r"(a[3]), "r"(b[0]), "r"(b[1]));
}

// Swizzled smem byte offset for (row, 16B-chunk c16) inside a 128x32-bf16 tile:
// rows are 64 B = 4 chunks; XOR with (row>>1)&3 -> ldmatrix conflict-free.
__device__ __forceinline__ uint32_t sw_off(int row, int c16) {
    return (uint32_t)(row * 64 + ((c16 ^ ((row >> 1) & 3)) << 4));
}

// ---------------------------------------------------------------------------
// bf16x3 NT GEMM via mma.sync:
//   C[128,128] tile = (Ahi+Alo)[M,K] @ (Bhi+Blo)[N,K]^T, fp32 accumulate.
// Output either fp32*alpha (outF) or hi/lo bf16 split (outHi/outLo).
// ---------------------------------------------------------------------------
__global__ __launch_bounds__(256, 1) void gemm_mma(
    const __nv_bfloat16* __restrict__ Ahi, const __nv_bfloat16* __restrict__ Alo,
    const __nv_bfloat16* __restrict__ Bhi, const __nv_bfloat16* __restrict__ Blo,
    float* __restrict__ outF,
    __nv_bfloat16* __restrict__ outHi, __nv_bfloat16* __restrict__ outLo,
    int lda, int ldb, int ldc, long sA, long sB, long sC,
    float alpha, int Ktot, int causalSkip, int causalK)
{
    const int m0 = blockIdx.y * BM;
    const int n0 = blockIdx.x * BN;
    if (causalSkip && n0 >= m0 + BM) return;

    extern __shared__ char smem[];
    const uint32_t sb = smem_u32(smem);

    const int tid  = threadIdx.x;
    const int lane = tid & 31;
    const int wid  = tid >> 5;
    const int warpM0 = (wid >> 2) * 64;   // 2 warps along M
    const int warpN0 = (wid & 3) * 32;    // 4 warps along N

    Ahi += (size_t)blockIdx.z * sA;  Alo += (size_t)blockIdx.z * sA;
    Bhi += (size_t)blockIdx.z * sB;  Blo += (size_t)blockIdx.z * sB;

    const int kEnd = causalK ? min(Ktot, m0 + BM) : Ktot;
    const int nCh = kEnd / BK;

    // global load coords for this thread (2 x 16B per matrix per chunk)
    int gr[2], gc[2];
#pragma unroll
    for (int r = 0; r < 2; r++) {
        int i = tid + r * 256;
        gr[r] = i >> 2;        // row 0..127
        gc[r] = i & 3;         // 16B chunk 0..3
    }

    auto issue = [&](int c) {
        const uint32_t st = sb + (uint32_t)(c & (STAGES - 1)) * STAGE_BYTES;
        const int k0 = c * BK;
#pragma unroll
        for (int r = 0; r < 2; r++) {
            const int row = gr[r], c16 = gc[r];
            const uint32_t so = sw_off(row, c16);
            const size_t ao = (size_t)(m0 + row) * lda + k0 + c16 * 8;
            const size_t bo = (size_t)(n0 + row) * ldb + k0 + c16 * 8;
            cp_async16(st + so,                 Ahi + ao);
            cp_async16(st + MAT_BYTES + so,     Alo + ao);
            cp_async16(st + 2 * MAT_BYTES + so, Bhi + bo);
            cp_async16(st + 3 * MAT_BYTES + so, Blo + bo);
        }
    };

    float acc[4][4][4];
#pragma unroll
    for (int i = 0; i < 4; i++)
#pragma unroll
        for (int j = 0; j < 4; j++)
#pragma unroll
            for (int k = 0; k < 4; k++) acc[i][j][k] = 0.f;

    // prologue: STAGES-1 groups (empty groups keep the count aligned)
#pragma unroll
    for (int s = 0; s < STAGES - 1; s++) {
        if (s < nCh) issue(s);
        CP_COMMIT();
    }

    // lane-invariant pieces of ldmatrix addresses
    const int aRow = (lane & 15);           // + warpM0 + mf*16
    const int aHi  = (lane >> 4);           // k-half select
    const int bRow = (lane & 7);            // + warpN0 + nf*8
    const int bHi  = ((lane >> 3) & 1);

    for (int c = 0; c < nCh; c++) {
        CP_WAIT2();
        __syncthreads();
        // refill the slot freed by iteration c-1
        if (c + STAGES - 1 < nCh) issue(c + STAGES - 1);
        CP_COMMIT();

        const uint32_t st = sb + (uint32_t)(c & (STAGES - 1)) * STAGE_BYTES;
#pragma unroll
        for (int ks = 0; ks < 2; ks++) {
            uint32_t ah[4][4], al[4][4], bh[4][2], bl[4][2];
#pragma unroll
            for (int mf = 0; mf < 4; mf++) {
                const int row = warpM0 + mf * 16 + aRow;
                const uint32_t so = sw_off(row, ks * 2 + aHi);
                ldmx4(ah[mf][0], ah[mf][1], ah[mf][2], ah[mf][3], st + so);
                ldmx4(al[mf][0], al[mf][1], al[mf][2], al[mf][3], st + MAT_BYTES + so);
            }
#pragma unroll
            for (int nf = 0; nf < 4; nf++) {
                const int row = warpN0 + nf * 8 + bRow;
                const uint32_t so = sw_off(row, ks * 2 + bHi);
                ldmx2(bh[nf][0], bh[nf][1], st + 2 * MAT_BYTES + so);
                ldmx2(bl[nf][0], bl[nf][1], st + 3 * MAT_BYTES + so);
            }
#pragma unroll
            for (int mf = 0; mf < 4; mf++)
#pragma unroll
                for (int nf = 0; nf < 4; nf++) {
                    mma16816(acc[mf][nf], ah[mf], bh[nf]);
                    mma16816(acc[mf][nf], ah[mf], bl[nf]);
                    mma16816(acc[mf][nf], al[mf], bh[nf]);
                }
        }
        __syncthreads();
    }
    CP_WAIT0();

    // epilogue
    const long cb = (long)blockIdx.z * sC;
    const int rBase = m0 + warpM0 + (lane >> 2);
    const int cBase = n0 + warpN0 + (lane & 3) * 2;
#pragma unroll
    for (int mf = 0; mf < 4; mf++) {
#pragma unroll
        for (int nf = 0; nf < 4; nf++) {
            const int col = cBase + nf * 8;
#pragma unroll
            for (int h = 0; h < 2; h++) {
                const int row = rBase + mf * 16 + h * 8;
                const float v0 = acc[mf][nf][2 * h];
                const float v1 = acc[mf][nf][2 * h + 1];
                if (outF) {
                    float2 w = make_float2(v0 * alpha, v1 * alpha);
                    *(float2*)(outF + cb + (size_t)row * ldc + col) = w;
                } else {
                    __nv_bfloat16 h0 = __float2bfloat16(v0);
                    __nv_bfloat16 h1 = __float2bfloat16(v1);
                    __nv_bfloat16 l0 = __float2bfloat16(v0 - __bfloat162float(h0));
                    __nv_bfloat16 l1 = __float2bfloat16(v1 - __bfloat162float(h1));
                    *(__nv_bfloat162*)(outHi + cb + (size_t)row * ldc + col) =
                        __halves2bfloat162(h0, h1);
                    *(__nv_bfloat162*)(outLo + cb + (size_t)row * ldc + col) =
                        __halves2bfloat162(l0, l1);
                }
            }
        }
    }
}

// ---------------------------------------------------------------------------
__global__ __launch_bounds__(256) void split_hi_lo(
    const float* __restrict__ src, __nv_bfloat16* __restrict__ hi,
    __nv_bfloat16* __restrict__ lo, int n4)
{
    int i = blockIdx.x * 256 + threadIdx.x;
    if (i >= n4) return;
    float4 v = ((const float4*)src)[i];
    __nv_bfloat16 h0 = __float2bfloat16(v.x), h1 = __float2bfloat16(v.y);
    __nv_bfloat16 h2 = __float2bfloat16(v.z), h3 = __float2bfloat16(v.w);
    __nv_bfloat16 l0 = __float2bfloat16(v.x - __bfloat162float(h0));
    __nv_bfloat16 l1 = __float2bfloat16(v.y - __bfloat162float(h1));
    __nv_bfloat16 l2 = __float2bfloat16(v.z - __bfloat162float(h2));
    __nv_bfloat16 l3 = __float2bfloat16(v.w - __bfloat162float(h3));
    __nv_bfloat162* H = (__nv_bfloat162*)hi + 2 * (size_t)i;
    __nv_bfloat162* L = (__nv_bfloat162*)lo + 2 * (size_t)i;
    H[0] = __halves2bfloat162(h0, h1); H[1] = __halves2bfloat162(h2, h3);
    L[0] = __halves2bfloat162(l0, l1); L[1] = __halves2bfloat162(l2, l3);
}

// src [B][SEQ][DM] -> dst [B][DM][SEQ]
__global__ __launch_bounds__(256) void transpose_bf16(
    const __nv_bfloat16* __restrict__ src, __nv_bfloat16* __restrict__ dst)
{
    __shared__ __nv_bfloat16 t[64][65];
    const int b  = blockIdx.z;
    const int n0 = blockIdx.x * 64;
    const int k0 = blockIdx.y * 64;
    const int tx = threadIdx.x & 31, ty = threadIdx.x >> 5;

    const __nv_bfloat16* s = src + ((size_t)b * SEQ + k0) * DM + n0;
#pragma unroll
    for (int i = 0; i < 8; i++) {
        int r = ty + i * 8;
        __nv_bfloat162 v = *(const __nv_bfloat162*)(s + (size_t)r * DM + 2 * tx);
        t[r][2*tx] = v.x; t[r][2*tx+1] = v.y;
    }
    __syncthreads();
    __nv_bfloat16* d = dst + ((size_t)b * DM + n0) * SEQ + k0;
#pragma unroll
    for (int i = 0; i < 8; i++) {
        int rn = ty + i * 8;
        *(__nv_bfloat162*)(d + (size_t)rn * SEQ + 2 * tx) =
            __halves2bfloat162(t[2*tx][rn], t[2*tx+1][rn]);
    }
}

// Causal softmax: fp32 in, bf16 hi/lo out, zero-fill to the 128-boundary.
__global__ __launch_bounds__(256) void softmax_causal(
    const float* __restrict__ P, __nv_bfloat16* __restrict__ Phi,
    __nv_bfloat16* __restrict__ Plo)
{
    const int q = blockIdx.x, b = blockIdx.y;
    const float* row = P + ((size_t)b * SEQ + q) * SEQ;
    __nv_bfloat16* hr = Phi + ((size_t)b * SEQ + q) * SEQ;
    __nv_bfloat16* lr = Plo + ((size_t)b * SEQ + q) * SEQ;
    const int len = q + 1, tid = threadIdx.x;

    __shared__ float sred[8];
    __shared__ float sbc;

    float vals[8]; int n = 0;
    float m = -CUDART_INF_F;
    for (int i = tid; i < len; i += 256) { float v = row[i]; vals[n++] = v; m = fmaxf(m, v); }
#pragma unroll
    for (int o = 16; o; o >>= 1) m = fmaxf(m, __shfl_xor_sync(0xffffffffu, m, o));
    if ((tid & 31) == 0) sred[tid >> 5] = m;
    __syncthreads();
    if (tid == 0) {
        float t = sred[0];
#pragma unroll
        for (int w = 1; w < 8; w++) t = fmaxf(t, sred[w]);
        sbc = t;
    }
    __syncthreads();
    m = sbc;

    float s = 0.f;
#pragma unroll
    for (int k = 0; k < 8; k++)
        if (k < n) { float e = expf(vals[k] - m); vals[k] = e; s += e; }
#pragma unroll
    for (int o = 16; o; o >>= 1) s += __shfl_xor_sync(0xffffffffu, s, o);
    __syncthreads();
    if ((tid & 31) == 0) sred[tid >> 5] = s;
    __syncthreads();
    if (tid == 0) {
        float t = 0.f;
#pragma unroll
        for (int w = 0; w < 8; w++) t += sred[w];
        sbc = 1.f / t;
    }
    __syncthreads();
    const float inv = sbc;

    n = 0;
    for (int i = tid; i < len; i += 256) {
        float e = vals[n++] * inv;
        __nv_bfloat16 h = __float2bfloat16(e);
        hr[i] = h;
        lr[i] = __float2bfloat16(e - __bfloat162float(h));
    }
    const __nv_bfloat16 z = __float2bfloat16(0.f);
    const int tileEnd = ((q >> 7) + 1) << 7;
    for (int i = len + tid; i < tileEnd; i += 256) { hr[i] = z; lr[i] = z; }
}

// ---------------------------------------------------------------------------
extern "C" void kernel_launch(void* const* d_in, const int* in_sizes, int n_in,
                              void* d_out, int out_size)
{
    const float* x  = (const float*)d_in[0];
    const float* Wq = (const float*)d_in[1];
    const float* Wk = (const float*)d_in[2];
    const float* Wv = (const float*)d_in[3];
    float* out = (float*)d_out;

    __nv_bfloat16 *xhi, *xlo, *Whi, *Wlo, *QKVhi, *QKVlo, *Vthi, *Vtlo, *Phi, *Plo;
    float* P;
    cudaGetSymbolAddress((void**)&xhi, g_xhi);     cudaGetSymbolAddress((void**)&xlo, g_xlo);
    cudaGetSymbolAddress((void**)&Whi, g_Whi);     cudaGetSymbolAddress((void**)&Wlo, g_Wlo);
    cudaGetSymbolAddress((void**)&QKVhi, g_QKVhi); cudaGetSymbolAddress((void**)&QKVlo, g_QKVlo);
    cudaGetSymbolAddress((void**)&Vthi, g_Vthi);   cudaGetSymbolAddress((void**)&Vtlo, g_Vtlo);
    cudaGetSymbolAddress((void**)&P, g_P);
    cudaGetSymbolAddress((void**)&Phi, g_Phi);     cudaGetSymbolAddress((void**)&Plo, g_Plo);

    const long BSD = (long)BATCH * SEQ * DM;
    const long SD  = (long)SEQ * DM;
    const long SS  = (long)SEQ * SEQ;

    cudaFuncSetAttribute(gemm_mma, cudaFuncAttributeMaxDynamicSharedMemorySize, SMEM_TOTAL);

    // 1) hi/lo splits
    split_hi_lo<<<(BATCH*SEQ*DM/4 + 255)/256, 256>>>(x, xhi, xlo, BATCH*SEQ*DM/4);
    split_hi_lo<<<(DM*DM/4 + 255)/256, 256>>>(Wq, Whi,            Wlo,            DM*DM/4);
    split_hi_lo<<<(DM*DM/4 + 255)/256, 256>>>(Wk, Whi + (long)DM*DM,   Wlo + (long)DM*DM,   DM*DM/4);
    split_hi_lo<<<(DM*DM/4 + 255)/256, 256>>>(Wv, Whi + 2L*DM*DM, Wlo + 2L*DM*DM, DM*DM/4);

    // 2) Fused QKV projection (z selects weight + output section; A fixed)
    {
        dim3 g(DM / BN, (BATCH * SEQ) / BM, 3);
        gemm_mma<<<g, 256, SMEM_TOTAL>>>(xhi, xlo, Whi, Wlo,
            nullptr, QKVhi, QKVlo,
            DM, DM, DM, 0, (long)DM * DM, BSD,
            1.f, DM, 0, 0);
    }

    // 3) V transpose: [B][S][DM] -> [B][DM][S]
    {
        dim3 g(DM / 64, SEQ / 64, BATCH);
        transpose_bf16<<<g, 256>>>(QKVhi + 2 * BSD, Vthi);
        transpose_bf16<<<g, 256>>>(QKVlo + 2 * BSD, Vtlo);
    }

    // 4) Scores: P = (1/32) Q @ K^T (causal tile skip)
    {
        dim3 g(SEQ / BN, SEQ / BM, BATCH);
        gemm_mma<<<g, 256, SMEM_TOTAL>>>(QKVhi, QKVlo, QKVhi + BSD, QKVlo + BSD,
            P, nullptr, nullptr,
            DM, DM, SEQ, SD, SD, SS,
            0.03125f, DM, 1, 0);
    }

    // 5) Causal softmax -> bf16 hi/lo P (+ zero fill to 128-boundary)
    softmax_causal<<<dim3(SEQ, BATCH), 256>>>(P, Phi, Plo);

    // 6) O = P @ V   (B operand = V^T, K-major over S; K truncated at diag)
    {
        dim3 g(DM / BN, SEQ / BM, BATCH);
        gemm_mma<<<g, 256, SMEM_TOTAL>>>(Phi, Plo, Vthi, Vtlo,
            out, nullptr, nullptr,
            SEQ, SEQ, DM, SS, SD, SD,
            1.f, SEQ, 0, 1);
    }
}